// round 5
// baseline (speedup 1.0000x reference)
#include <cuda_runtime.h>

#define TV 50000
#define TE 300
#define THE 512
#define THD 1024
#define TBB 64
#define TT 400
#define DEC 80

#define NB 148
#define NT 256

typedef unsigned long long u64;

// ---------------- device scratch (static; zero-init at load) ----------------
__device__ float d_gi[(size_t)2 * TT * TBB * 3 * THE];     // encoder input gates
__device__ float d_h[2 * TBB * THE];                       // encoder hidden
__device__ float d_ghp[(size_t)2 * 6 * TBB * 3 * THE];     // encoder gh partials
__device__ float d_hd[TBB * THD];                          // decoder hidden
__device__ float d_dgp[(size_t)6 * TBB * 3 * THD];         // decoder partials (2 gi + 4 gh)
__device__ u64 d_amax[DEC][TBB];                           // per-step argmax keys
__device__ unsigned d_cnt[8];                              // barrier counters

struct SM {
    float As[16][64];
    float Bs[16][128];
    const float* Aptr[64];
};

// ---------------- helpers ----------------
__device__ __forceinline__ void fma2(u64& acc, u64 a, u64 b) {
    asm("fma.rn.f32x2 %0, %1, %2, %0;" : "+l"(acc) : "l"(a), "l"(b));
}
__device__ __forceinline__ u64 dup2(float a) {
    u64 r; asm("mov.b64 %0, {%1, %1};" : "=l"(r) : "f"(a)); return r;
}
__device__ __forceinline__ float2 unpack2(u64 v) {
    float2 r; asm("mov.b64 {%0, %1}, %2;" : "=f"(r.x), "=f"(r.y) : "l"(v)); return r;
}
__device__ __forceinline__ float sigf(float x) { return 1.f / (1.f + expf(-x)); }

__device__ __forceinline__ u64 packkey(float f, int n) {
    unsigned u = __float_as_uint(f);
    u = ((int)u < 0) ? ~u : (u | 0x80000000u);
    return ((u64)u << 32) | (unsigned)(0xFFFFFFFFu - (unsigned)n);
}
__device__ __forceinline__ int key2tok(u64 key) {
    return (int)(0xFFFFFFFFu - (unsigned)(key & 0xFFFFFFFFull));
}

// grid barrier: 8 split counters, monotonic target; release via L2 polling
__device__ __forceinline__ void gridbar(unsigned target) {
    __syncthreads();
    if (threadIdx.x == 0) {
        __threadfence();
        atomicAdd(&d_cnt[blockIdx.x & 7], 1u);
        const uint4* p = (const uint4*)d_cnt;
        for (;;) {
            uint4 a = __ldcg(p), b = __ldcg(p + 1);
            unsigned s = a.x + a.y + a.z + a.w + b.x + b.y + b.z + b.w;
            if (s >= target) break;
            __nanosleep(128);
        }
        __threadfence();
    }
    __syncthreads();
}
#define BAR() gridbar(++nbar * NB)

// ---- 64x128 tile GEMM core (256 threads): acc += A[64xK] * B[nlim x K]^T ----
// A rows via sm.Aptr (ld.cg). B via ld.ca. acc[4][4]: m-pairs x 4 n columns.
__device__ __forceinline__ void mmtile(
    SM& sm, const float* __restrict__ B, int ldb, int n0, int nlim,
    int k0, int kend, u64 (&acc)[4][4])
{
    const int tid = threadIdx.x;
    const int am = tid & 63, ak = (tid >> 6) * 4;
    const int bn = tid & 127, kq = (tid >> 7) * 8;
    const int w  = tid >> 5,  ng4 = (tid & 31) * 4;

#pragma unroll
    for (int i = 0; i < 4; i++)
#pragma unroll
        for (int j = 0; j < 4; j++) acc[i][j] = 0ull;

    const float* Arow = sm.Aptr[am];
    const float* Brow = (n0 + bn < nlim) ? (B + (size_t)(n0 + bn) * ldb) : nullptr;

    for (int kb = k0; kb < kend; kb += 16) {
        __syncthreads();
        if (kb + 16 <= kend) {
            float4 av = __ldcg((const float4*)(Arow + kb + ak));
            sm.As[ak + 0][am] = av.x; sm.As[ak + 1][am] = av.y;
            sm.As[ak + 2][am] = av.z; sm.As[ak + 3][am] = av.w;
            float4 b0 = make_float4(0.f, 0.f, 0.f, 0.f), b1 = b0;
            if (Brow) {
                b0 = __ldg((const float4*)(Brow + kb + kq));
                b1 = __ldg((const float4*)(Brow + kb + kq + 4));
            }
            sm.Bs[kq + 0][bn] = b0.x; sm.Bs[kq + 1][bn] = b0.y;
            sm.Bs[kq + 2][bn] = b0.z; sm.Bs[kq + 3][bn] = b0.w;
            sm.Bs[kq + 4][bn] = b1.x; sm.Bs[kq + 5][bn] = b1.y;
            sm.Bs[kq + 6][bn] = b1.z; sm.Bs[kq + 7][bn] = b1.w;
        } else {
#pragma unroll
            for (int j = 0; j < 4; j++) {
                int k = kb + ak + j;
                sm.As[ak + j][am] = (k < kend) ? __ldcg(Arow + k) : 0.f;
            }
#pragma unroll
            for (int j = 0; j < 8; j++) {
                int k = kb + kq + j;
                sm.Bs[kq + j][bn] = (Brow && k < kend) ? __ldg(Brow + k) : 0.f;
            }
        }
        __syncthreads();

#pragma unroll
        for (int kk = 0; kk < 16; kk++) {
            u64 ap[4];
#pragma unroll
            for (int i = 0; i < 4; i++)
                ap[i] = *(const u64*)&sm.As[kk][w * 8 + 2 * i];
            float4 bv = *(const float4*)&sm.Bs[kk][ng4];
            u64 bd0 = dup2(bv.x), bd1 = dup2(bv.y), bd2 = dup2(bv.z), bd3 = dup2(bv.w);
#pragma unroll
            for (int i = 0; i < 4; i++) {
                fma2(acc[i][0], ap[i], bd0);
                fma2(acc[i][1], ap[i], bd1);
                fma2(acc[i][2], ap[i], bd2);
                fma2(acc[i][3], ap[i], bd3);
            }
        }
    }
}

__device__ __forceinline__ void store_tile(float* C, int ldc, int n0,
                                           const u64 (&acc)[4][4]) {
    const int w = threadIdx.x >> 5, ng4 = (threadIdx.x & 31) * 4;
#pragma unroll
    for (int i = 0; i < 4; i++) {
        int m0 = w * 8 + 2 * i;
#pragma unroll
        for (int j = 0; j < 4; j++) {
            float2 v = unpack2(acc[i][j]);
            __stcg(C + (size_t)m0 * ldc + n0 + ng4 + j, v.x);
            __stcg(C + (size_t)(m0 + 1) * ldc + n0 + ng4 + j, v.y);
        }
    }
}

__device__ __forceinline__ void logits_epi(int n0, const u64 (&acc)[4][4],
                                           const float* __restrict__ outb,
                                           u64* __restrict__ amax) {
    const int w = threadIdx.x >> 5, ng4 = (threadIdx.x & 31) * 4;
    const int lane = threadIdx.x & 31;
    u64 best[8];
#pragma unroll
    for (int r = 0; r < 8; r++) best[r] = 0ull;
#pragma unroll
    for (int j = 0; j < 4; j++) {
        int n = n0 + ng4 + j;
        if (n < TV) {
            float bb = __ldg(outb + n);
#pragma unroll
            for (int i = 0; i < 4; i++) {
                float2 v = unpack2(acc[i][j]);
                u64 k0 = packkey(v.x + bb, n);
                u64 k1 = packkey(v.y + bb, n);
                if (k0 > best[2 * i])     best[2 * i] = k0;
                if (k1 > best[2 * i + 1]) best[2 * i + 1] = k1;
            }
        }
    }
#pragma unroll
    for (int o = 16; o > 0; o >>= 1) {
#pragma unroll
        for (int r = 0; r < 8; r++) {
            u64 v = __shfl_xor_sync(0xFFFFFFFFu, best[r], o);
            if (v > best[r]) best[r] = v;
        }
    }
    if (lane == 0) {
#pragma unroll
        for (int r = 0; r < 8; r++) atomicMax(&amax[w * 8 + r], best[r]);
    }
}

__device__ __forceinline__ int kcb(int i) { return (i <= 2) ? 96 * i : 192 + 80 * (i - 2); }

// ---------------- the single persistent kernel ----------------
__global__ void __launch_bounds__(NT, 1) k_main(
    const int* __restrict__ texts, const int* __restrict__ lens,
    const float* __restrict__ emb,
    const float* __restrict__ wihf, const float* __restrict__ whhf,
    const float* __restrict__ bihf, const float* __restrict__ bhhf,
    const float* __restrict__ wihb, const float* __restrict__ whhb,
    const float* __restrict__ bihb, const float* __restrict__ bhhb,
    const float* __restrict__ dwih, const float* __restrict__ dwhh,
    const float* __restrict__ dbih, const float* __restrict__ dbhh,
    const float* __restrict__ outw, const float* __restrict__ outb,
    float* __restrict__ out)
{
    __shared__ SM sm;
    const int bid = blockIdx.x, tid = threadIdx.x;
    unsigned nbar = 0;
    u64 acc[4][4];

    // phase 0: zero encoder hidden
    for (int idx = bid * NT + tid; idx < 2 * TBB * THE; idx += NB * NT)
        __stcg(&d_h[idx], 0.f);
    BAR();

    // ---- PRE: gi[z][t] = emb[texts[:,t]] @ wih_z^T  (9600 tile jobs) ----
    for (int job = bid; job < 2 * TT * 12; job += NB) {
        int z = job / (TT * 12);
        int r = job % (TT * 12);
        int t = r / 12, nt = r % 12;
        if (tid < 64)
            sm.Aptr[tid] = emb + (size_t)__ldg(&texts[tid * TT + t]) * TE;
        __syncthreads();
        mmtile(sm, z ? wihb : wihf, TE, nt * 128, 3 * THE, 0, TE, acc);
        store_tile(d_gi + (size_t)(z * TT + t) * TBB * (3 * THE), 3 * THE, nt * 128, acc);
    }
    BAR();

    // ---- ENCODER: 400 steps ----
    for (int step = 0; step < TT; step++) {
        // E1: gh partials: z(2) x ntile(12) x kc(6) = 144 jobs
        for (int job = bid; job < 144; job += NB) {
            int z = job / 72, r = job % 72;
            int nt = r / 6, kc = r % 6;
            if (tid < 64) sm.Aptr[tid] = d_h + z * TBB * THE + tid * THE;
            __syncthreads();
            mmtile(sm, z ? whhb : whhf, THE, nt * 128, 3 * THE, kcb(kc), kcb(kc + 1), acc);
            store_tile(d_ghp + (size_t)(z * 6 + kc) * TBB * (3 * THE), 3 * THE, nt * 128, acc);
        }
        BAR();
        // E2: gate update
        for (int idx = bid * NT + tid; idx < 2 * TBB * THE; idx += NB * NT) {
            int z = idx >> 15, b = (idx >> 9) & 63, j = idx & 511;
            int tt = z ? (TT - 1 - step) : step;
            if (tt < __ldg(&lens[b])) {
                float s0 = 0.f, s1 = 0.f, s2 = 0.f;
                const float* p = d_ghp + (size_t)z * 6 * TBB * (3 * THE) + (size_t)b * (3 * THE);
#pragma unroll
                for (int kc = 0; kc < 6; kc++, p += (size_t)TBB * (3 * THE)) {
                    s0 += __ldcg(p + j);
                    s1 += __ldcg(p + THE + j);
                    s2 += __ldcg(p + 2 * THE + j);
                }
                const float* gi = d_gi + (size_t)((z * TT + tt) * TBB + b) * (3 * THE);
                const float* bih = z ? bihb : bihf;
                const float* bhh = z ? bhhb : bhhf;
                float rr = sigf(__ldcg(gi + j) + __ldg(bih + j) + s0 + __ldg(bhh + j));
                float zz = sigf(__ldcg(gi + THE + j) + __ldg(bih + THE + j) + s1 + __ldg(bhh + THE + j));
                float nn = tanhf(__ldcg(gi + 2 * THE + j) + __ldg(bih + 2 * THE + j)
                                 + rr * (s2 + __ldg(bhh + 2 * THE + j)));
                float* hp = d_h + z * TBB * THE + b * THE + j;
                float h = __ldcg(hp);
                __stcg(hp, (1.f - zz) * nn + zz * h);
            }
        }
        BAR();
    }

    // ---- hinit: hdec = concat(h_fwd, h_bwd) ----
    for (int idx = bid * NT + tid; idx < TBB * THD; idx += NB * NT) {
        int b = idx >> 10, j = idx & 1023;
        float v = (j < THE) ? __ldcg(&d_h[b * THE + j])
                            : __ldcg(&d_h[TBB * THE + b * THE + (j - THE)]);
        __stcg(&d_hd[idx], v);
    }
    BAR();

    // ---- DECODER: 80 steps ----
    for (int s = 0; s < DEC; s++) {
        // D1: gi (48 jobs) + gh (96 jobs)
        for (int job = bid; job < 144; job += NB) {
            if (job < 48) {
                int nt = job >> 1, kc = job & 1;
                if (tid < 64) {
                    int tk = (s == 0) ? 1 : key2tok(__ldcg(&d_amax[s - 1][tid]));
                    sm.Aptr[tid] = emb + (size_t)tk * TE;
                }
                __syncthreads();
                mmtile(sm, dwih, TE, nt * 128, 3 * THD, kc ? 160 : 0, kc ? 300 : 160, acc);
                store_tile(d_dgp + (size_t)kc * TBB * (3 * THD), 3 * THD, nt * 128, acc);
            } else {
                int j2 = job - 48;
                int nt = j2 >> 2, kc = j2 & 3;
                if (tid < 64) sm.Aptr[tid] = d_hd + tid * THD;
                __syncthreads();
                mmtile(sm, dwhh, THD, nt * 128, 3 * THD, kc * 256, kc * 256 + 256, acc);
                store_tile(d_dgp + (size_t)(2 + kc) * TBB * (3 * THD), 3 * THD, nt * 128, acc);
            }
        }
        if (bid == NB - 1 && tid < 64 && s > 0)
            out[tid * DEC + (s - 1)] = (float)key2tok(__ldcg(&d_amax[s - 1][tid]));
        BAR();
        // D2: gate update
        for (int idx = bid * NT + tid; idx < TBB * THD; idx += NB * NT) {
            int b = idx >> 10, j = idx & 1023;
            float g0 = 0.f, g1 = 0.f, g2 = 0.f, s0 = 0.f, s1 = 0.f, s2 = 0.f;
            const float* p = d_dgp + (size_t)b * (3 * THD);
#pragma unroll
            for (int kc = 0; kc < 2; kc++, p += (size_t)TBB * (3 * THD)) {
                g0 += __ldcg(p + j); g1 += __ldcg(p + THD + j); g2 += __ldcg(p + 2 * THD + j);
            }
#pragma unroll
            for (int kc = 0; kc < 4; kc++, p += (size_t)TBB * (3 * THD)) {
                s0 += __ldcg(p + j); s1 += __ldcg(p + THD + j); s2 += __ldcg(p + 2 * THD + j);
            }
            float rr = sigf(g0 + __ldg(dbih + j) + s0 + __ldg(dbhh + j));
            float zz = sigf(g1 + __ldg(dbih + THD + j) + s1 + __ldg(dbhh + THD + j));
            float nn = tanhf(g2 + __ldg(dbih + 2 * THD + j) + rr * (s2 + __ldg(dbhh + 2 * THD + j)));
            float h = __ldcg(&d_hd[idx]);
            __stcg(&d_hd[idx], (1.f - zz) * nn + zz * h);
        }
        BAR();
        // D3: logits + fused argmax (391 full-K tile jobs)
        for (int job = bid; job < (TV + 127) / 128; job += NB) {
            if (tid < 64) sm.Aptr[tid] = d_hd + tid * THD;
            __syncthreads();
            mmtile(sm, outw, THD, job * 128, TV, 0, THD, acc);
            logits_epi(job * 128, acc, outb, &d_amax[s][0]);
        }
        BAR();
    }

    if (bid == NB - 1 && tid < 64)
        out[tid * DEC + (DEC - 1)] = (float)key2tok(__ldcg(&d_amax[DEC - 1][tid]));
    BAR();

    // cleanup for next replay: zero amax keys and barrier counters
    for (int idx = bid * NT + tid; idx < DEC * TBB; idx += NB * NT)
        ((u64*)d_amax)[idx] = 0ull;
    if (bid == 0 && tid < 8) d_cnt[tid] = 0u;
}

// ---------------- host launcher ----------------
extern "C" void kernel_launch(void* const* d_in, const int* in_sizes, int n_in,
                              void* d_out, int out_size)
{
    k_main<<<NB, NT>>>(
        (const int*)d_in[0], (const int*)d_in[1], (const float*)d_in[2],
        (const float*)d_in[3], (const float*)d_in[4], (const float*)d_in[5],
        (const float*)d_in[6], (const float*)d_in[7], (const float*)d_in[8],
        (const float*)d_in[9], (const float*)d_in[10], (const float*)d_in[11],
        (const float*)d_in[12], (const float*)d_in[13], (const float*)d_in[14],
        (const float*)d_in[15], (const float*)d_in[16], (float*)d_out);
}

// round 6
// speedup vs baseline: 1.2483x; 1.2483x over previous
#include <cuda_runtime.h>

#define TV 50000
#define TE 300
#define THE 512
#define THD 1024
#define TBB 64
#define TT 400
#define DEC 80

#define NB 296
#define NT 256

typedef unsigned long long u64;

// ---------------- device scratch (static; zero-init at load) ----------------
__device__ float d_gi[(size_t)2 * TT * TBB * 3 * THE];     // encoder input gates
__device__ float d_h[2 * TBB * THE];                       // encoder hidden
__device__ float d_ghp[(size_t)2 * 6 * TBB * 3 * THE];     // encoder gh partials
__device__ float d_hd[TBB * THD];                          // decoder hidden
__device__ float d_dgp[(size_t)6 * TBB * 3 * THD];         // decoder partials (2 gi + 4 gh)
__device__ u64 d_amax[DEC][TBB];                           // per-step argmax keys
__device__ unsigned d_cnt[8];                              // barrier counters

struct SM {
    float As[2][16][64];
    float Bs[2][16][128];
    const float* Aptr[64];
};

// ---------------- helpers ----------------
__device__ __forceinline__ void fma2(u64& acc, u64 a, u64 b) {
    asm("fma.rn.f32x2 %0, %1, %2, %0;" : "+l"(acc) : "l"(a), "l"(b));
}
__device__ __forceinline__ u64 dup2(float a) {
    u64 r; asm("mov.b64 %0, {%1, %1};" : "=l"(r) : "f"(a)); return r;
}
__device__ __forceinline__ float2 unpack2(u64 v) {
    float2 r; asm("mov.b64 {%0, %1}, %2;" : "=f"(r.x), "=f"(r.y) : "l"(v)); return r;
}
__device__ __forceinline__ float sigf(float x) { return 1.f / (1.f + expf(-x)); }

__device__ __forceinline__ u64 packkey(float f, int n) {
    unsigned u = __float_as_uint(f);
    u = ((int)u < 0) ? ~u : (u | 0x80000000u);
    return ((u64)u << 32) | (unsigned)(0xFFFFFFFFu - (unsigned)n);
}
__device__ __forceinline__ int key2tok(u64 key) {
    return (int)(0xFFFFFFFFu - (unsigned)(key & 0xFFFFFFFFull));
}

// grid barrier: 8 split counters, monotonic target; release via L2 polling
__device__ __forceinline__ void gridbar(unsigned target) {
    __syncthreads();
    if (threadIdx.x == 0) {
        __threadfence();
        atomicAdd(&d_cnt[blockIdx.x & 7], 1u);
        const uint4* p = (const uint4*)d_cnt;
        for (;;) {
            uint4 a = __ldcg(p), b = __ldcg(p + 1);
            unsigned s = a.x + a.y + a.z + a.w + b.x + b.y + b.z + b.w;
            if (s >= target) break;
            __nanosleep(96);
        }
        __threadfence();
    }
    __syncthreads();
}
#define BAR() gridbar(++nbar * NB)

// ---- staged loaders (global -> registers) ----
__device__ __forceinline__ void loadA(const float* __restrict__ Arow,
                                      int kb, int kend, int ak, float (&a)[4]) {
    if (kb + 16 <= kend) {
        float4 v = __ldcg((const float4*)(Arow + kb + ak));
        a[0] = v.x; a[1] = v.y; a[2] = v.z; a[3] = v.w;
    } else {
#pragma unroll
        for (int j = 0; j < 4; j++) {
            int k = kb + ak + j;
            a[j] = (k < kend) ? __ldcg(Arow + k) : 0.f;
        }
    }
}
__device__ __forceinline__ void loadB(const float* __restrict__ Brow,
                                      int kb, int kend, int kq, float (&b)[8]) {
    if (Brow && kb + 16 <= kend) {
        float4 v0 = __ldg((const float4*)(Brow + kb + kq));
        float4 v1 = __ldg((const float4*)(Brow + kb + kq + 4));
        b[0] = v0.x; b[1] = v0.y; b[2] = v0.z; b[3] = v0.w;
        b[4] = v1.x; b[5] = v1.y; b[6] = v1.z; b[7] = v1.w;
    } else {
#pragma unroll
        for (int j = 0; j < 8; j++) {
            int k = kb + kq + j;
            b[j] = (Brow && k < kend) ? __ldg(Brow + k) : 0.f;
        }
    }
}
__device__ __forceinline__ void stageS(SM& sm, int buf, int ak, int am, int kq, int bn,
                                       const float (&a)[4], const float (&b)[8]) {
#pragma unroll
    for (int j = 0; j < 4; j++) sm.As[buf][ak + j][am] = a[j];
#pragma unroll
    for (int j = 0; j < 8; j++) sm.Bs[buf][kq + j][bn] = b[j];
}

// ---- 64x128 tile GEMM core (256 threads, double-buffered) ----
// acc += A[64 x K] * B[nlim x K]^T ; A rows via sm.Aptr (ld.cg), B via ld.ca
__device__ __forceinline__ void mmtile(
    SM& sm, const float* __restrict__ B, int ldb, int n0, int nlim,
    int k0, int kend, u64 (&acc)[4][4])
{
    const int tid = threadIdx.x;
    const int am = tid & 63, ak = (tid >> 6) * 4;
    const int bn = tid & 127, kq = (tid >> 7) * 8;
    const int w  = tid >> 5,  ng4 = (tid & 31) * 4;

#pragma unroll
    for (int i = 0; i < 4; i++)
#pragma unroll
        for (int j = 0; j < 4; j++) acc[i][j] = 0ull;

    const float* Arow = sm.Aptr[am];
    const float* Brow = (n0 + bn < nlim) ? (B + (size_t)(n0 + bn) * ldb) : nullptr;

    const int nblk = (kend - k0 + 15) >> 4;

    float a[4]; float b[8];
    loadA(Arow, k0, kend, ak, a);
    loadB(Brow, k0, kend, kq, b);
    stageS(sm, 0, ak, am, kq, bn, a, b);
    __syncthreads();

    for (int i = 0; i < nblk; i++) {
        const int buf = i & 1;
        if (i + 1 < nblk) {               // prefetch next slab into regs
            int kb = k0 + (i + 1) * 16;
            loadA(Arow, kb, kend, ak, a);
            loadB(Brow, kb, kend, kq, b);
        }
#pragma unroll
        for (int kk = 0; kk < 16; kk++) {
            u64 ap[4];
#pragma unroll
            for (int q = 0; q < 4; q++)
                ap[q] = *(const u64*)&sm.As[buf][kk][w * 8 + 2 * q];
            float4 bv = *(const float4*)&sm.Bs[buf][kk][ng4];
            u64 bd0 = dup2(bv.x), bd1 = dup2(bv.y), bd2 = dup2(bv.z), bd3 = dup2(bv.w);
#pragma unroll
            for (int q = 0; q < 4; q++) {
                fma2(acc[q][0], ap[q], bd0);
                fma2(acc[q][1], ap[q], bd1);
                fma2(acc[q][2], ap[q], bd2);
                fma2(acc[q][3], ap[q], bd3);
            }
        }
        if (i + 1 < nblk)
            stageS(sm, buf ^ 1, ak, am, kq, bn, a, b);
        __syncthreads();
    }
}

__device__ __forceinline__ void store_tile(float* C, int ldc, int n0,
                                           const u64 (&acc)[4][4]) {
    const int w = threadIdx.x >> 5, ng4 = (threadIdx.x & 31) * 4;
#pragma unroll
    for (int i = 0; i < 4; i++) {
        int m0 = w * 8 + 2 * i;
#pragma unroll
        for (int j = 0; j < 4; j++) {
            float2 v = unpack2(acc[i][j]);
            __stcg(C + (size_t)m0 * ldc + n0 + ng4 + j, v.x);
            __stcg(C + (size_t)(m0 + 1) * ldc + n0 + ng4 + j, v.y);
        }
    }
}

__device__ __forceinline__ void logits_epi(int n0, const u64 (&acc)[4][4],
                                           const float* __restrict__ outb,
                                           u64* __restrict__ amax) {
    const int w = threadIdx.x >> 5, ng4 = (threadIdx.x & 31) * 4;
    const int lane = threadIdx.x & 31;
    u64 best[8];
#pragma unroll
    for (int r = 0; r < 8; r++) best[r] = 0ull;
#pragma unroll
    for (int j = 0; j < 4; j++) {
        int n = n0 + ng4 + j;
        if (n < TV) {
            float bb = __ldg(outb + n);
#pragma unroll
            for (int i = 0; i < 4; i++) {
                float2 v = unpack2(acc[i][j]);
                u64 k0 = packkey(v.x + bb, n);
                u64 k1 = packkey(v.y + bb, n);
                if (k0 > best[2 * i])     best[2 * i] = k0;
                if (k1 > best[2 * i + 1]) best[2 * i + 1] = k1;
            }
        }
    }
#pragma unroll
    for (int o = 16; o > 0; o >>= 1) {
#pragma unroll
        for (int r = 0; r < 8; r++) {
            u64 v = __shfl_xor_sync(0xFFFFFFFFu, best[r], o);
            if (v > best[r]) best[r] = v;
        }
    }
    if (lane == 0) {
#pragma unroll
        for (int r = 0; r < 8; r++) atomicMax(&amax[w * 8 + r], best[r]);
    }
}

__device__ __forceinline__ int kcb(int i) { return (i <= 2) ? 96 * i : 192 + 80 * (i - 2); }

// ---------------- the single persistent kernel ----------------
__global__ void __launch_bounds__(NT, 2) k_main(
    const int* __restrict__ texts, const int* __restrict__ lens,
    const float* __restrict__ emb,
    const float* __restrict__ wihf, const float* __restrict__ whhf,
    const float* __restrict__ bihf, const float* __restrict__ bhhf,
    const float* __restrict__ wihb, const float* __restrict__ whhb,
    const float* __restrict__ bihb, const float* __restrict__ bhhb,
    const float* __restrict__ dwih, const float* __restrict__ dwhh,
    const float* __restrict__ dbih, const float* __restrict__ dbhh,
    const float* __restrict__ outw, const float* __restrict__ outb,
    float* __restrict__ out)
{
    __shared__ SM sm;
    const int bid = blockIdx.x, tid = threadIdx.x;
    unsigned nbar = 0;
    u64 acc[4][4];

    // phase 0: zero encoder hidden
    for (int idx = bid * NT + tid; idx < 2 * TBB * THE; idx += NB * NT)
        __stcg(&d_h[idx], 0.f);
    BAR();

    // ---- PRE: gi[z][t] = emb[texts[:,t]] @ wih_z^T  (9600 tile jobs) ----
    for (int job = bid; job < 2 * TT * 12; job += NB) {
        int z = job / (TT * 12);
        int r = job % (TT * 12);
        int t = r / 12, nt = r % 12;
        if (tid < 64)
            sm.Aptr[tid] = emb + (size_t)__ldg(&texts[tid * TT + t]) * TE;
        __syncthreads();
        mmtile(sm, z ? wihb : wihf, TE, nt * 128, 3 * THE, 0, TE, acc);
        store_tile(d_gi + (size_t)(z * TT + t) * TBB * (3 * THE), 3 * THE, nt * 128, acc);
    }
    BAR();

    // ---- ENCODER: 400 steps ----
    for (int step = 0; step < TT; step++) {
        // E1: gh partials: z(2) x ntile(12) x kc(6) = 144 jobs
        for (int job = bid; job < 144; job += NB) {
            int z = job / 72, r = job % 72;
            int nt = r / 6, kc = r % 6;
            if (tid < 64) sm.Aptr[tid] = d_h + z * TBB * THE + tid * THE;
            __syncthreads();
            mmtile(sm, z ? whhb : whhf, THE, nt * 128, 3 * THE, kcb(kc), kcb(kc + 1), acc);
            store_tile(d_ghp + (size_t)(z * 6 + kc) * TBB * (3 * THE), 3 * THE, nt * 128, acc);
        }
        BAR();
        // E2: gate update
        for (int idx = bid * NT + tid; idx < 2 * TBB * THE; idx += NB * NT) {
            int z = idx >> 15, b = (idx >> 9) & 63, j = idx & 511;
            int tt = z ? (TT - 1 - step) : step;
            if (tt < __ldg(&lens[b])) {
                float s0 = 0.f, s1 = 0.f, s2 = 0.f;
                const float* p = d_ghp + (size_t)z * 6 * TBB * (3 * THE) + (size_t)b * (3 * THE);
#pragma unroll
                for (int kc = 0; kc < 6; kc++, p += (size_t)TBB * (3 * THE)) {
                    s0 += __ldcg(p + j);
                    s1 += __ldcg(p + THE + j);
                    s2 += __ldcg(p + 2 * THE + j);
                }
                const float* gi = d_gi + (size_t)((z * TT + tt) * TBB + b) * (3 * THE);
                const float* bih = z ? bihb : bihf;
                const float* bhh = z ? bhhb : bhhf;
                float rr = sigf(__ldcg(gi + j) + __ldg(bih + j) + s0 + __ldg(bhh + j));
                float zz = sigf(__ldcg(gi + THE + j) + __ldg(bih + THE + j) + s1 + __ldg(bhh + THE + j));
                float nn = tanhf(__ldcg(gi + 2 * THE + j) + __ldg(bih + 2 * THE + j)
                                 + rr * (s2 + __ldg(bhh + 2 * THE + j)));
                float* hp = d_h + z * TBB * THE + b * THE + j;
                float h = __ldcg(hp);
                __stcg(hp, (1.f - zz) * nn + zz * h);
            }
        }
        BAR();
    }

    // ---- hinit: hdec = concat(h_fwd, h_bwd) ----
    for (int idx = bid * NT + tid; idx < TBB * THD; idx += NB * NT) {
        int b = idx >> 10, j = idx & 1023;
        float v = (j < THE) ? __ldcg(&d_h[b * THE + j])
                            : __ldcg(&d_h[TBB * THE + b * THE + (j - THE)]);
        __stcg(&d_hd[idx], v);
    }
    BAR();

    // ---- DECODER: 80 steps ----
    for (int s = 0; s < DEC; s++) {
        // D1: gi (48 jobs) + gh (96 jobs)
        for (int job = bid; job < 144; job += NB) {
            if (job < 48) {
                int nt = job >> 1, kc = job & 1;
                if (tid < 64) {
                    int tk = (s == 0) ? 1 : key2tok(__ldcg(&d_amax[s - 1][tid]));
                    sm.Aptr[tid] = emb + (size_t)tk * TE;
                }
                __syncthreads();
                mmtile(sm, dwih, TE, nt * 128, 3 * THD, kc ? 160 : 0, kc ? 300 : 160, acc);
                store_tile(d_dgp + (size_t)kc * TBB * (3 * THD), 3 * THD, nt * 128, acc);
            } else {
                int j2 = job - 48;
                int nt = j2 >> 2, kc = j2 & 3;
                if (tid < 64) sm.Aptr[tid] = d_hd + tid * THD;
                __syncthreads();
                mmtile(sm, dwhh, THD, nt * 128, 3 * THD, kc * 256, kc * 256 + 256, acc);
                store_tile(d_dgp + (size_t)(2 + kc) * TBB * (3 * THD), 3 * THD, nt * 128, acc);
            }
        }
        if (bid == NB - 1 && tid < 64 && s > 0)
            out[tid * DEC + (s - 1)] = (float)key2tok(__ldcg(&d_amax[s - 1][tid]));
        BAR();
        // D2: gate update
        for (int idx = bid * NT + tid; idx < TBB * THD; idx += NB * NT) {
            int b = idx >> 10, j = idx & 1023;
            float g0 = 0.f, g1 = 0.f, g2 = 0.f, s0 = 0.f, s1 = 0.f, s2 = 0.f;
            const float* p = d_dgp + (size_t)b * (3 * THD);
#pragma unroll
            for (int kc = 0; kc < 2; kc++, p += (size_t)TBB * (3 * THD)) {
                g0 += __ldcg(p + j); g1 += __ldcg(p + THD + j); g2 += __ldcg(p + 2 * THD + j);
            }
#pragma unroll
            for (int kc = 0; kc < 4; kc++, p += (size_t)TBB * (3 * THD)) {
                s0 += __ldcg(p + j); s1 += __ldcg(p + THD + j); s2 += __ldcg(p + 2 * THD + j);
            }
            float rr = sigf(g0 + __ldg(dbih + j) + s0 + __ldg(dbhh + j));
            float zz = sigf(g1 + __ldg(dbih + THD + j) + s1 + __ldg(dbhh + THD + j));
            float nn = tanhf(g2 + __ldg(dbih + 2 * THD + j) + rr * (s2 + __ldg(dbhh + 2 * THD + j)));
            float h = __ldcg(&d_hd[idx]);
            __stcg(&d_hd[idx], (1.f - zz) * nn + zz * h);
        }
        BAR();
        // D3: logits + fused argmax (391 full-K tile jobs)
        for (int job = bid; job < (TV + 127) / 128; job += NB) {
            if (tid < 64) sm.Aptr[tid] = d_hd + tid * THD;
            __syncthreads();
            mmtile(sm, outw, THD, job * 128, TV, 0, THD, acc);
            logits_epi(job * 128, acc, outb, &d_amax[s][0]);
        }
        BAR();
    }

    if (bid == NB - 1 && tid < 64)
        out[tid * DEC + (DEC - 1)] = (float)key2tok(__ldcg(&d_amax[DEC - 1][tid]));
    BAR();

    // cleanup for next replay: zero amax keys and barrier counters
    for (int idx = bid * NT + tid; idx < DEC * TBB; idx += NB * NT)
        ((u64*)d_amax)[idx] = 0ull;
    if (bid == 0 && tid < 8) d_cnt[tid] = 0u;
}

// ---------------- host launcher ----------------
extern "C" void kernel_launch(void* const* d_in, const int* in_sizes, int n_in,
                              void* d_out, int out_size)
{
    k_main<<<NB, NT>>>(
        (const int*)d_in[0], (const int*)d_in[1], (const float*)d_in[2],
        (const float*)d_in[3], (const float*)d_in[4], (const float*)d_in[5],
        (const float*)d_in[6], (const float*)d_in[7], (const float*)d_in[8],
        (const float*)d_in[9], (const float*)d_in[10], (const float*)d_in[11],
        (const float*)d_in[12], (const float*)d_in[13], (const float*)d_in[14],
        (const float*)d_in[15], (const float*)d_in[16], (float*)d_out);
}

// round 8
// speedup vs baseline: 1.2960x; 1.0382x over previous
#include <cuda_runtime.h>

#define TV 50000
#define TE 300
#define THE 512
#define THD 1024
#define TBB 64
#define TT 400
#define DEC 80

#define NB 296
#define NT 256

typedef unsigned long long u64;

// ---------------- device scratch (static; zero-init at load) ----------------
__device__ float d_gi[(size_t)2 * TT * TBB * 3 * THE];     // encoder input gates
__device__ float d_h[2 * TBB * THE];                       // encoder hidden
__device__ float d_ghp[(size_t)2 * 6 * TBB * 3 * THE];     // encoder gh partials
__device__ float d_hd[TBB * THD];                          // decoder hidden
__device__ float d_dgp[(size_t)6 * TBB * 3 * THD];         // decoder partials (2 gi + 4 gh)
__device__ u64 d_amax[DEC][TBB];                           // per-step argmax keys
__device__ unsigned d_cnt[8];                              // barrier counters

struct SM {
    float As[2][16][64];
    float Bs[2][16][128];
    const float* Aptr[64];
};

// ---------------- helpers ----------------
__device__ __forceinline__ void fma2(u64& acc, u64 a, u64 b) {
    asm("fma.rn.f32x2 %0, %1, %2, %0;" : "+l"(acc) : "l"(a), "l"(b));
}
__device__ __forceinline__ u64 dup2(float a) {
    u64 r; asm("mov.b64 %0, {%1, %1};" : "=l"(r) : "f"(a)); return r;
}
__device__ __forceinline__ u64 pack2(float x, float y) {
    u64 r; asm("mov.b64 %0, {%1, %2};" : "=l"(r) : "f"(x), "f"(y)); return r;
}
__device__ __forceinline__ float2 unpack2(u64 v) {
    float2 r; asm("mov.b64 {%0, %1}, %2;" : "=f"(r.x), "=f"(r.y) : "l"(v)); return r;
}
__device__ __forceinline__ float sigf(float x) { return 1.f / (1.f + expf(-x)); }

__device__ __forceinline__ u64 packkey(float f, int n) {
    unsigned u = __float_as_uint(f);
    u = ((int)u < 0) ? ~u : (u | 0x80000000u);
    return ((u64)u << 32) | (unsigned)(0xFFFFFFFFu - (unsigned)n);
}
__device__ __forceinline__ int key2tok(u64 key) {
    return (int)(0xFFFFFFFFu - (unsigned)(key & 0xFFFFFFFFull));
}

// grid barrier: 8 split counters, monotonic target; release via L2 polling
__device__ __forceinline__ void gridbar(unsigned target) {
    __syncthreads();
    if (threadIdx.x == 0) {
        __threadfence();
        atomicAdd(&d_cnt[blockIdx.x & 7], 1u);
        const uint4* p = (const uint4*)d_cnt;
        for (;;) {
            uint4 a = __ldcg(p), b = __ldcg(p + 1);
            unsigned s = a.x + a.y + a.z + a.w + b.x + b.y + b.z + b.w;
            if (s >= target) break;
            __nanosleep(96);
        }
        __threadfence();
    }
    __syncthreads();
}
#define BAR() gridbar(++nbar * NB)

// ---- staged loaders (global -> registers) ----
__device__ __forceinline__ void loadA(const float* __restrict__ Arow,
                                      int kb, int kend, int ak, float (&a)[4]) {
    if (kb + 16 <= kend) {
        float4 v = __ldcg((const float4*)(Arow + kb + ak));
        a[0] = v.x; a[1] = v.y; a[2] = v.z; a[3] = v.w;
    } else {
#pragma unroll
        for (int j = 0; j < 4; j++) {
            int k = kb + ak + j;
            a[j] = (k < kend) ? __ldcg(Arow + k) : 0.f;
        }
    }
}
__device__ __forceinline__ void loadB(const float* __restrict__ Brow,
                                      int kb, int kend, int kq, float (&b)[8]) {
    if (Brow && kb + 16 <= kend) {
        float4 v0 = __ldg((const float4*)(Brow + kb + kq));
        float4 v1 = __ldg((const float4*)(Brow + kb + kq + 4));
        b[0] = v0.x; b[1] = v0.y; b[2] = v0.z; b[3] = v0.w;
        b[4] = v1.x; b[5] = v1.y; b[6] = v1.z; b[7] = v1.w;
    } else {
#pragma unroll
        for (int j = 0; j < 8; j++) {
            int k = kb + kq + j;
            b[j] = (Brow && k < kend) ? __ldg(Brow + k) : 0.f;
        }
    }
}
__device__ __forceinline__ void stageS(SM& sm, int buf, int ak, int am, int kq, int bn,
                                       const float (&a)[4], const float (&b)[8]) {
#pragma unroll
    for (int j = 0; j < 4; j++) sm.As[buf][ak + j][am] = a[j];
#pragma unroll
    for (int j = 0; j < 8; j++) sm.Bs[buf][kq + j][bn] = b[j];
}

// ---- 64x128 tile GEMM core (256 threads, double-buffered, hand-pipelined) ----
// acc += A[64 x K] * B[nlim x K]^T ; A rows via sm.Aptr (ld.cg), B via ld.ca
__device__ __forceinline__ void mmtile(
    SM& sm, const float* __restrict__ B, int ldb, int n0, int nlim,
    int k0, int kend, u64 (&acc)[4][4])
{
    const int tid = threadIdx.x;
    const int am = tid & 63, ak = (tid >> 6) * 4;
    const int bn = tid & 127, kq = (tid >> 7) * 8;
    const int w  = tid >> 5,  ng4 = (tid & 31) * 4;

#pragma unroll
    for (int i = 0; i < 4; i++)
#pragma unroll
        for (int j = 0; j < 4; j++) acc[i][j] = 0ull;

    const float* Arow = sm.Aptr[am];
    const float* Brow = (n0 + bn < nlim) ? (B + (size_t)(n0 + bn) * ldb) : nullptr;

    const int nblk = (kend - k0 + 15) >> 4;

    float a[4]; float b[8];
    loadA(Arow, k0, kend, ak, a);
    loadB(Brow, k0, kend, kq, b);
    stageS(sm, 0, ak, am, kq, bn, a, b);
    __syncthreads();

    for (int i = 0; i < nblk; i++) {
        const int buf = i & 1;
        if (i + 1 < nblk) {               // prefetch next slab into regs
            int kb = k0 + (i + 1) * 16;
            loadA(Arow, kb, kend, ak, a);
            loadB(Brow, kb, kend, kq, b);
        }
        // hand-pipelined 16-deep FFMA2 loop: kk+1 operands loaded before kk math
        float4 a0 = *(const float4*)&sm.As[buf][0][w * 8];
        float4 a1 = *(const float4*)&sm.As[buf][0][w * 8 + 4];
        float4 bv = *(const float4*)&sm.Bs[buf][0][ng4];
#pragma unroll
        for (int kk = 0; kk < 16; kk++) {
            float4 ta0, ta1, tbv;
            if (kk + 1 < 16) {
                ta0 = *(const float4*)&sm.As[buf][kk + 1][w * 8];
                ta1 = *(const float4*)&sm.As[buf][kk + 1][w * 8 + 4];
                tbv = *(const float4*)&sm.Bs[buf][kk + 1][ng4];
            }
            u64 ap0 = pack2(a0.x, a0.y), ap1 = pack2(a0.z, a0.w);
            u64 ap2 = pack2(a1.x, a1.y), ap3 = pack2(a1.z, a1.w);
            u64 bd0 = dup2(bv.x), bd1 = dup2(bv.y), bd2 = dup2(bv.z), bd3 = dup2(bv.w);
            fma2(acc[0][0], ap0, bd0); fma2(acc[1][0], ap1, bd0);
            fma2(acc[2][0], ap2, bd0); fma2(acc[3][0], ap3, bd0);
            fma2(acc[0][1], ap0, bd1); fma2(acc[1][1], ap1, bd1);
            fma2(acc[2][1], ap2, bd1); fma2(acc[3][1], ap3, bd1);
            fma2(acc[0][2], ap0, bd2); fma2(acc[1][2], ap1, bd2);
            fma2(acc[2][2], ap2, bd2); fma2(acc[3][2], ap3, bd2);
            fma2(acc[0][3], ap0, bd3); fma2(acc[1][3], ap1, bd3);
            fma2(acc[2][3], ap2, bd3); fma2(acc[3][3], ap3, bd3);
            if (kk + 1 < 16) { a0 = ta0; a1 = ta1; bv = tbv; }
        }
        if (i + 1 < nblk)
            stageS(sm, buf ^ 1, ak, am, kq, bn, a, b);
        __syncthreads();
    }
}

__device__ __forceinline__ void store_tile(float* C, int ldc, int n0,
                                           const u64 (&acc)[4][4]) {
    const int w = threadIdx.x >> 5, ng4 = (threadIdx.x & 31) * 4;
#pragma unroll
    for (int i = 0; i < 4; i++) {
        int m0 = w * 8 + 2 * i;
        float2 v0 = unpack2(acc[i][0]), v1 = unpack2(acc[i][1]);
        float2 v2 = unpack2(acc[i][2]), v3 = unpack2(acc[i][3]);
        float4 r0 = make_float4(v0.x, v1.x, v2.x, v3.x);
        float4 r1 = make_float4(v0.y, v1.y, v2.y, v3.y);
        __stcg((float4*)(C + (size_t)m0 * ldc + n0 + ng4), r0);
        __stcg((float4*)(C + (size_t)(m0 + 1) * ldc + n0 + ng4), r1);
    }
}

__device__ __forceinline__ void logits_epi(int n0, const u64 (&acc)[4][4],
                                           const float* __restrict__ outb,
                                           u64* __restrict__ amax) {
    const int w = threadIdx.x >> 5, ng4 = (threadIdx.x & 31) * 4;
    const int lane = threadIdx.x & 31;
    u64 best[8];
#pragma unroll
    for (int r = 0; r < 8; r++) best[r] = 0ull;
#pragma unroll
    for (int j = 0; j < 4; j++) {
        int n = n0 + ng4 + j;
        if (n < TV) {
            float bb = __ldg(outb + n);
#pragma unroll
            for (int i = 0; i < 4; i++) {
                float2 v = unpack2(acc[i][j]);
                u64 k0 = packkey(v.x + bb, n);
                u64 k1 = packkey(v.y + bb, n);
                if (k0 > best[2 * i])     best[2 * i] = k0;
                if (k1 > best[2 * i + 1]) best[2 * i + 1] = k1;
            }
        }
    }
#pragma unroll
    for (int o = 16; o > 0; o >>= 1) {
#pragma unroll
        for (int r = 0; r < 8; r++) {
            u64 v = __shfl_xor_sync(0xFFFFFFFFu, best[r], o);
            if (v > best[r]) best[r] = v;
        }
    }
    if (lane == 0) {
#pragma unroll
        for (int r = 0; r < 8; r++) atomicMax(&amax[w * 8 + r], best[r]);
    }
}

__device__ __forceinline__ int kcb(int i) { return (i <= 2) ? 96 * i : 192 + 80 * (i - 2); }

// ---------------- the single persistent kernel ----------------
__global__ void __launch_bounds__(NT, 2) k_main(
    const int* __restrict__ texts, const int* __restrict__ lens,
    const float* __restrict__ emb,
    const float* __restrict__ wihf, const float* __restrict__ whhf,
    const float* __restrict__ bihf, const float* __restrict__ bhhf,
    const float* __restrict__ wihb, const float* __restrict__ whhb,
    const float* __restrict__ bihb, const float* __restrict__ bhhb,
    const float* __restrict__ dwih, const float* __restrict__ dwhh,
    const float* __restrict__ dbih, const float* __restrict__ dbhh,
    const float* __restrict__ outw, const float* __restrict__ outb,
    float* __restrict__ out)
{
    __shared__ SM sm;
    const int bid = blockIdx.x, tid = threadIdx.x;
    unsigned nbar = 0;
    u64 acc[4][4];

    // phase 0: zero encoder hidden
    for (int idx = bid * NT + tid; idx < 2 * TBB * THE; idx += NB * NT)
        __stcg(&d_h[idx], 0.f);
    BAR();

    // ---- PRE: gi[z][t] = emb[texts[:,t]] @ wih_z^T  (9600 tile jobs) ----
    for (int job = bid; job < 2 * TT * 12; job += NB) {
        int z = job / (TT * 12);
        int r = job % (TT * 12);
        int t = r / 12, nt = r % 12;
        if (tid < 64)
            sm.Aptr[tid] = emb + (size_t)__ldg(&texts[tid * TT + t]) * TE;
        __syncthreads();
        mmtile(sm, z ? wihb : wihf, TE, nt * 128, 3 * THE, 0, TE, acc);
        store_tile(d_gi + (size_t)(z * TT + t) * TBB * (3 * THE), 3 * THE, nt * 128, acc);
    }
    BAR();

    // ---- ENCODER: 400 steps ----
    for (int step = 0; step < TT; step++) {
        // E1: gh partials: z(2) x ntile(12) x kc(6) = 144 jobs
        for (int job = bid; job < 144; job += NB) {
            int z = job / 72, r = job % 72;
            int nt = r / 6, kc = r % 6;
            if (tid < 64) sm.Aptr[tid] = d_h + z * TBB * THE + tid * THE;
            __syncthreads();
            mmtile(sm, z ? whhb : whhf, THE, nt * 128, 3 * THE, kcb(kc), kcb(kc + 1), acc);
            store_tile(d_ghp + (size_t)(z * 6 + kc) * TBB * (3 * THE), 3 * THE, nt * 128, acc);
        }
        BAR();
        // E2: gate update
        for (int idx = bid * NT + tid; idx < 2 * TBB * THE; idx += NB * NT) {
            int z = idx >> 15, b = (idx >> 9) & 63, j = idx & 511;
            int tt = z ? (TT - 1 - step) : step;
            if (tt < __ldg(&lens[b])) {
                float s0 = 0.f, s1 = 0.f, s2 = 0.f;
                const float* p = d_ghp + (size_t)z * 6 * TBB * (3 * THE) + (size_t)b * (3 * THE);
#pragma unroll
                for (int kc = 0; kc < 6; kc++, p += (size_t)TBB * (3 * THE)) {
                    s0 += __ldcg(p + j);
                    s1 += __ldcg(p + THE + j);
                    s2 += __ldcg(p + 2 * THE + j);
                }
                const float* gi = d_gi + (size_t)((z * TT + tt) * TBB + b) * (3 * THE);
                const float* bih = z ? bihb : bihf;
                const float* bhh = z ? bhhb : bhhf;
                float rr = sigf(__ldcg(gi + j) + __ldg(bih + j) + s0 + __ldg(bhh + j));
                float zz = sigf(__ldcg(gi + THE + j) + __ldg(bih + THE + j) + s1 + __ldg(bhh + THE + j));
                float nn = tanhf(__ldcg(gi + 2 * THE + j) + __ldg(bih + 2 * THE + j)
                                 + rr * (s2 + __ldg(bhh + 2 * THE + j)));
                float* hp = d_h + z * TBB * THE + b * THE + j;
                float h = __ldcg(hp);
                __stcg(hp, (1.f - zz) * nn + zz * h);
            }
        }
        BAR();
    }

    // ---- hinit: hdec = concat(h_fwd, h_bwd) ----
    for (int idx = bid * NT + tid; idx < TBB * THD; idx += NB * NT) {
        int b = idx >> 10, j = idx & 1023;
        float v = (j < THE) ? __ldcg(&d_h[b * THE + j])
                            : __ldcg(&d_h[TBB * THE + b * THE + (j - THE)]);
        __stcg(&d_hd[idx], v);
    }
    BAR();

    // ---- DECODER: 80 steps ----
    for (int s = 0; s < DEC; s++) {
        // D1: gi (48 jobs) + gh (96 jobs)
        for (int job = bid; job < 144; job += NB) {
            if (job < 48) {
                int nt = job >> 1, kc = job & 1;
                if (tid < 64) {
                    int tk = (s == 0) ? 1 : key2tok(__ldcg(&d_amax[s - 1][tid]));
                    sm.Aptr[tid] = emb + (size_t)tk * TE;
                }
                __syncthreads();
                mmtile(sm, dwih, TE, nt * 128, 3 * THD, kc ? 160 : 0, kc ? 300 : 160, acc);
                store_tile(d_dgp + (size_t)kc * TBB * (3 * THD), 3 * THD, nt * 128, acc);
            } else {
                int j2 = job - 48;
                int nt = j2 >> 2, kc = j2 & 3;
                if (tid < 64) sm.Aptr[tid] = d_hd + tid * THD;
                __syncthreads();
                mmtile(sm, dwhh, THD, nt * 128, 3 * THD, kc * 256, kc * 256 + 256, acc);
                store_tile(d_dgp + (size_t)(2 + kc) * TBB * (3 * THD), 3 * THD, nt * 128, acc);
            }
        }
        if (bid == NB - 1 && tid < 64 && s > 0)
            out[tid * DEC + (s - 1)] = (float)key2tok(__ldcg(&d_amax[s - 1][tid]));
        BAR();
        // D2: gate update
        for (int idx = bid * NT + tid; idx < TBB * THD; idx += NB * NT) {
            int b = idx >> 10, j = idx & 1023;
            float g0 = 0.f, g1 = 0.f, g2 = 0.f, s0 = 0.f, s1 = 0.f, s2 = 0.f;
            const float* p = d_dgp + (size_t)b * (3 * THD);
#pragma unroll
            for (int kc = 0; kc < 2; kc++, p += (size_t)TBB * (3 * THD)) {
                g0 += __ldcg(p + j); g1 += __ldcg(p + THD + j); g2 += __ldcg(p + 2 * THD + j);
            }
#pragma unroll
            for (int kc = 0; kc < 4; kc++, p += (size_t)TBB * (3 * THD)) {
                s0 += __ldcg(p + j); s1 += __ldcg(p + THD + j); s2 += __ldcg(p + 2 * THD + j);
            }
            float rr = sigf(g0 + __ldg(dbih + j) + s0 + __ldg(dbhh + j));
            float zz = sigf(g1 + __ldg(dbih + THD + j) + s1 + __ldg(dbhh + THD + j));
            float nn = tanhf(g2 + __ldg(dbih + 2 * THD + j) + rr * (s2 + __ldg(dbhh + 2 * THD + j)));
            float h = __ldcg(&d_hd[idx]);
            __stcg(&d_hd[idx], (1.f - zz) * nn + zz * h);
        }
        BAR();
        // D3: logits + fused argmax (391 full-K tile jobs)
        for (int job = bid; job < (TV + 127) / 128; job += NB) {
            if (tid < 64) sm.Aptr[tid] = d_hd + tid * THD;
            __syncthreads();
            mmtile(sm, outw, THD, job * 128, TV, 0, THD, acc);
            logits_epi(job * 128, acc, outb, &d_amax[s][0]);
        }
        BAR();
    }

    if (bid == NB - 1 && tid < 64)
        out[tid * DEC + (DEC - 1)] = (float)key2tok(__ldcg(&d_amax[DEC - 1][tid]));
    BAR();

    // cleanup for next replay: zero amax keys and barrier counters
    for (int idx = bid * NT + tid; idx < DEC * TBB; idx += NB * NT)
        ((u64*)d_amax)[idx] = 0ull;
    if (bid == 0 && tid < 8) d_cnt[tid] = 0u;
}

// ---------------- host launcher ----------------
extern "C" void kernel_launch(void* const* d_in, const int* in_sizes, int n_in,
                              void* d_out, int out_size)
{
    k_main<<<NB, NT>>>(
        (const int*)d_in[0], (const int*)d_in[1], (const float*)d_in[2],
        (const float*)d_in[3], (const float*)d_in[4], (const float*)d_in[5],
        (const float*)d_in[6], (const float*)d_in[7], (const float*)d_in[8],
        (const float*)d_in[9], (const float*)d_in[10], (const float*)d_in[11],
        (const float*)d_in[12], (const float*)d_in[13], (const float*)d_in[14],
        (const float*)d_in[15], (const float*)d_in[16], (float*)d_out);
}